// round 12
// baseline (speedup 1.0000x reference)
#include <cuda_runtime.h>
#include <cuda_fp16.h>
#include <math.h>
#include <stdint.h>

#define BATCH 4096
#define MSET  8192
#define DIM   1024
#define HID   4096
#define OUTD  1000
#define OUTP  1024
#define CAP   2048

// ---------------- scratch (static device globals: no allocation) ----------------
__device__ __half g_XNh[(size_t)BATCH * DIM];
__device__ __half g_YNh[(size_t)MSET  * DIM];
__device__ __half g_Mh [(size_t)MSET  * DIM];     // raw memory_set in half
__device__ float  g_S  [(size_t)BATCH * MSET];
__device__ __half g_FIh[(size_t)BATCH * 2 * DIM];
__device__ __half g_Hh [(size_t)BATCH * HID];
__device__ float  g_Hp [(size_t)BATCH * HID];     // fp32 partial of H (enc-half K)
__device__ __half g_W1h[(size_t)HID * 2 * DIM];
__device__ __half g_W2h[(size_t)OUTP * HID];     // rows 1000..1023 zero-padded

// ---------------- helpers ----------------
__device__ __forceinline__ void cpa16(void* sdst, const void* gsrc) {
    unsigned s = (unsigned)__cvta_generic_to_shared(sdst);
    asm volatile("cp.async.cg.shared.global [%0], [%1], 16;\n" :: "r"(s), "l"(gsrc) : "memory");
}
#define CPA_COMMIT() asm volatile("cp.async.commit_group;\n" ::: "memory")
#define CPA_WAIT1()  asm volatile("cp.async.wait_group 1;\n" ::: "memory")

__device__ __forceinline__ void ldsm_x4(unsigned& r0, unsigned& r1, unsigned& r2, unsigned& r3,
                                        const __half* p) {
    unsigned a = (unsigned)__cvta_generic_to_shared(p);
    asm volatile("ldmatrix.sync.aligned.m8n8.x4.shared.b16 {%0,%1,%2,%3}, [%4];"
                 : "=r"(r0), "=r"(r1), "=r"(r2), "=r"(r3) : "r"(a));
}

__device__ __forceinline__ void mma_fp16(float c[4], const unsigned a[4], const unsigned b[2]) {
    asm volatile(
        "mma.sync.aligned.m16n8k16.row.col.f32.f16.f16.f32 "
        "{%0,%1,%2,%3}, {%4,%5,%6,%7}, {%8,%9}, {%0,%1,%2,%3};\n"
        : "+f"(c[0]), "+f"(c[1]), "+f"(c[2]), "+f"(c[3])
        : "r"(a[0]), "r"(a[1]), "r"(a[2]), "r"(a[3]), "r"(b[0]), "r"(b[1]));
}

__device__ __forceinline__ float warp_sum(float v) {
#pragma unroll
    for (int o = 16; o > 0; o >>= 1) v += __shfl_down_sync(0xffffffffu, v, o);
    return v;
}
__device__ __forceinline__ float warp_max(float v) {
#pragma unroll
    for (int o = 16; o > 0; o >>= 1) v = fmaxf(v, __shfl_down_sync(0xffffffffu, v, o));
    return v;
}
__device__ __forceinline__ float block_sum(float v, float* buf) {
    int tid = threadIdx.x, w = tid >> 5, l = tid & 31;
    v = warp_sum(v);
    __syncthreads();
    if (l == 0) buf[w] = v;
    __syncthreads();
    if (tid == 0) {
        float s = 0.f;
#pragma unroll
        for (int i = 0; i < 8; i++) s += buf[i];
        buf[0] = s;
    }
    __syncthreads();
    return buf[0];
}
__device__ __forceinline__ float2 block_sum2(float a, float b, float2* buf) {
    int tid = threadIdx.x, w = tid >> 5, l = tid & 31;
#pragma unroll
    for (int o = 16; o > 0; o >>= 1) {
        a += __shfl_down_sync(0xffffffffu, a, o);
        b += __shfl_down_sync(0xffffffffu, b, o);
    }
    __syncthreads();
    if (l == 0) buf[w] = make_float2(a, b);
    __syncthreads();
    if (tid == 0) {
        float2 s = make_float2(0.f, 0.f);
#pragma unroll
        for (int i = 0; i < 8; i++) { s.x += buf[i].x; s.y += buf[i].y; }
        buf[0] = s;
    }
    __syncthreads();
    return buf[0];
}
__device__ __forceinline__ float block_max(float v, float* buf) {
    int tid = threadIdx.x, w = tid >> 5, l = tid & 31;
    v = warp_max(v);
    __syncthreads();
    if (l == 0) buf[w] = v;
    __syncthreads();
    if (tid == 0) {
        float s = buf[0];
#pragma unroll
        for (int i = 1; i < 8; i++) s = fmaxf(s, buf[i]);
        buf[0] = s;
    }
    __syncthreads();
    return buf[0];
}

// ---------------- 1) fused prep ----------------
#define PREP_BLOCKS (BATCH + MSET + 8192 + 4096)

__global__ __launch_bounds__(256) void prep_kernel(const float* __restrict__ enc,
                                                   const float* __restrict__ mem,
                                                   const float* __restrict__ W1,
                                                   const float* __restrict__ W2) {
    __shared__ float buf[8];
    int b = blockIdx.x;
    int tid = threadIdx.x;

    if (b < BATCH + MSET) {
        bool is_enc = (b < BATCH);
        const float* src = is_enc ? enc : mem;
        __half* dst = is_enc ? g_XNh : g_YNh;
        size_t row = is_enc ? b : (b - BATCH);
        const float4* s4 = reinterpret_cast<const float4*>(src) + row * (DIM / 4);
        float4 v = s4[tid];

        {
            __half2 h0 = __floats2half2_rn(v.x, v.y);
            __half2 h1 = __floats2half2_rn(v.z, v.w);
            uint2 u = make_uint2(*reinterpret_cast<unsigned*>(&h0), *reinterpret_cast<unsigned*>(&h1));
            if (is_enc)
                reinterpret_cast<uint2*>(g_FIh)[row * 512 + tid] = u;
            else
                reinterpret_cast<uint2*>(g_Mh)[row * 256 + tid] = u;
        }

        float ss = v.x * v.x + v.y * v.y + v.z * v.z + v.w * v.w;
        ss = block_sum(ss, buf);
        float inv = rsqrtf(ss + 1e-6f);
        __half2 h0 = __floats2half2_rn(v.x * inv, v.y * inv);
        __half2 h1 = __floats2half2_rn(v.z * inv, v.w * inv);
        uint2 u = make_uint2(*reinterpret_cast<unsigned*>(&h0), *reinterpret_cast<unsigned*>(&h1));
        reinterpret_cast<uint2*>(dst)[row * (DIM / 4) + tid] = u;
    } else if (b < BATCH + MSET + 8192) {
        int i = (b - (BATCH + MSET)) * 256 + tid;
        float4 v = reinterpret_cast<const float4*>(W1)[i];
        __half2 h0 = __floats2half2_rn(v.x, v.y);
        __half2 h1 = __floats2half2_rn(v.z, v.w);
        uint2 u = make_uint2(*reinterpret_cast<unsigned*>(&h0), *reinterpret_cast<unsigned*>(&h1));
        reinterpret_cast<uint2*>(g_W1h)[i] = u;
    } else {
        int i = (b - (BATCH + MSET + 8192)) * 256 + tid;
        uint2 u = make_uint2(0u, 0u);
        if (i < OUTD * HID / 4) {
            float4 v = reinterpret_cast<const float4*>(W2)[i];
            __half2 h0 = __floats2half2_rn(v.x, v.y);
            __half2 h1 = __floats2half2_rn(v.z, v.w);
            u = make_uint2(*reinterpret_cast<unsigned*>(&h0), *reinterpret_cast<unsigned*>(&h1));
        }
        reinterpret_cast<uint2*>(g_W2h)[i] = u;
    }
}

// ---------------- 2) fp16 tensor-core NT GEMM (R11 config, generalized K window) ----
// 128x128 CTA tile, BK=64, 8 warps (4M x 2N, 32x64 warp tile), ldmatrix.x4,
// mma m16n8k16, 3-stage cp.async, 256 threads, 2 CTAs/SM.
// MODE 0: A=g_XNh, B=g_YNh  -> g_S (float)
// MODE 2: A=g_Hh,  B=g_W2h  -> Cext (float, +bias, N-guard)
// MODE 3: A=g_FIh, B=g_W1h  -> g_Hp (float partial, no bias)
// MODE 4: A=g_FIh, B=g_W1h  -> g_Hh (half, acc + g_Hp + bias, relu)
#define HSTRIDE 72
#define MAT_H (128 * HSTRIDE)
#define STAGE_H (2 * MAT_H)
#define NST 3
#define GEMM_SMEM_BYTES (NST * STAGE_H * 2)   // 110592

template <int MODE, bool BIAS, bool RELU, bool NGUARD>
__global__ __launch_bounds__(256, 2) void gemm_fp16(const float* __restrict__ bias,
                                                    float* __restrict__ Cext,
                                                    int N, int K, int ldk, int koff) {
    extern __shared__ __half sh[];

    const __half* A;
    const __half* B;
    if (MODE == 0)      { A = g_XNh; B = g_YNh; }
    else if (MODE == 2) { A = g_Hh;  B = g_W2h; }
    else                { A = g_FIh; B = g_W1h; }

    int tid = threadIdx.x;
    int lane = tid & 31;
    int warp = tid >> 5;
    int wm = warp & 3, wn = warp >> 2;
    int g = lane >> 2, tig = lane & 3;

    int bm = blockIdx.y * 128;
    int bn = blockIdx.x * 128;

    float acc[2][8][4];
#pragma unroll
    for (int i = 0; i < 2; i++)
#pragma unroll
        for (int j = 0; j < 8; j++)
#pragma unroll
            for (int q = 0; q < 4; q++) acc[i][j][q] = 0.f;

    int kT = K >> 6;
    const __half* Abase = A + (size_t)bm * ldk + koff;
    const __half* Bbase = B + (size_t)bn * ldk + koff;

    auto load_stage = [&](int t) {
        int st = t % NST;
        __half* sA = sh + st * STAGE_H;
        __half* sB = sA + MAT_H;
        const __half* Ag = Abase + t * 64;
        const __half* Bg = Bbase + t * 64;
#pragma unroll
        for (int it = 0; it < 4; it++) {
            int idx = it * 256 + tid;
            int row = idx >> 3, ch = idx & 7;
            cpa16(sA + row * HSTRIDE + ch * 8, Ag + (size_t)row * ldk + ch * 8);
            cpa16(sB + row * HSTRIDE + ch * 8, Bg + (size_t)row * ldk + ch * 8);
        }
    };

    load_stage(0); CPA_COMMIT();
    load_stage(1); CPA_COMMIT();

    int a_row = lane & 15;
    int a_kh  = (lane >> 4) << 3;
    int b_q   = lane >> 3;
    int b_row = (b_q >> 1) * 8 + (lane & 7);
    int b_kh  = (b_q & 1) << 3;

    for (int t = 0; t < kT; t++) {
        CPA_WAIT1();
        __syncthreads();

        if (t + 2 < kT) { load_stage(t + 2); CPA_COMMIT(); }

        const __half* as = sh + (t % NST) * STAGE_H + (wm * 32) * HSTRIDE;
        const __half* bs = sh + (t % NST) * STAGE_H + MAT_H + (wn * 64) * HSTRIDE;

#pragma unroll
        for (int kk = 0; kk < 4; kk++) {
            int kb = kk * 16;
            unsigned a[2][4], b[8][2];
#pragma unroll
            for (int i = 0; i < 2; i++)
                ldsm_x4(a[i][0], a[i][1], a[i][2], a[i][3],
                        as + (i * 16 + a_row) * HSTRIDE + kb + a_kh);
#pragma unroll
            for (int jj = 0; jj < 4; jj++)
                ldsm_x4(b[2 * jj][0], b[2 * jj][1], b[2 * jj + 1][0], b[2 * jj + 1][1],
                        bs + (jj * 16 + b_row) * HSTRIDE + kb + b_kh);
#pragma unroll
            for (int i = 0; i < 2; i++)
#pragma unroll
                for (int j = 0; j < 8; j++)
                    mma_fp16(acc[i][j], a[i], b[j]);
        }
    }

    // epilogue
#pragma unroll
    for (int i = 0; i < 2; i++) {
        int r0 = bm + wm * 32 + i * 16 + g;
#pragma unroll
        for (int j = 0; j < 8; j++) {
            int col = bn + wn * 64 + j * 8 + tig * 2;
            if (NGUARD && col >= N) continue;
            float bv0 = 0.f, bv1 = 0.f;
            if (BIAS) { bv0 = __ldg(bias + col); bv1 = __ldg(bias + col + 1); }
            float v0 = acc[i][j][0] + bv0;
            float v1 = acc[i][j][1] + bv1;
            float v2 = acc[i][j][2] + bv0;
            float v3 = acc[i][j][3] + bv1;
            if (MODE == 4) {
                float2 p0 = *reinterpret_cast<const float2*>(g_Hp + (size_t)r0 * N + col);
                float2 p1 = *reinterpret_cast<const float2*>(g_Hp + (size_t)(r0 + 8) * N + col);
                v0 += p0.x; v1 += p0.y; v2 += p1.x; v3 += p1.y;
            }
            if (RELU) {
                v0 = fmaxf(v0, 0.f); v1 = fmaxf(v1, 0.f);
                v2 = fmaxf(v2, 0.f); v3 = fmaxf(v3, 0.f);
            }
            if (MODE == 4) {
                __half2 h0 = __floats2half2_rn(v0, v1);
                __half2 h1 = __floats2half2_rn(v2, v3);
                *reinterpret_cast<unsigned*>(g_Hh + (size_t)r0 * N + col) =
                    *reinterpret_cast<unsigned*>(&h0);
                *reinterpret_cast<unsigned*>(g_Hh + (size_t)(r0 + 8) * N + col) =
                    *reinterpret_cast<unsigned*>(&h1);
            } else {
                float* C = (MODE == 0) ? g_S : (MODE == 3) ? g_Hp : Cext;
                *reinterpret_cast<float2*>(C + (size_t)r0 * N + col)       = make_float2(v0, v1);
                *reinterpret_cast<float2*>(C + (size_t)(r0 + 8) * N + col) = make_float2(v2, v3);
            }
        }
    }
}

// ---------------- 3) fused sparsemax + memory_vector -> FIh right half ----------------
__global__ __launch_bounds__(256) void sparsemax_mv_kernel() {
    __shared__ float zbuf[MSET];
    __shared__ float bufA[8];
    __shared__ float2 buf2[8];
    __shared__ int sh_pos;
    int* lidx = reinterpret_cast<int*>(zbuf);
    float* lw  = zbuf + CAP;

    size_t row = blockIdx.x;
    int tid = threadIdx.x;
    const float4* s4 = reinterpret_cast<const float4*>(g_S + row * (size_t)MSET);

    float4 r[8];
    float mx = -1e30f;
#pragma unroll
    for (int q = 0; q < 8; q++) {
        r[q] = s4[q * 256 + tid];
        mx = fmaxf(mx, fmaxf(fmaxf(r[q].x, r[q].y), fmaxf(r[q].z, r[q].w)));
    }
    mx = block_max(mx, bufA);

    float tau = mx - 1.0f;
    for (int it = 0; it < 64; ++it) {
        float s = 0.f, c = 0.f;
#pragma unroll
        for (int q = 0; q < 8; q++) {
            if (r[q].x > tau) { s += r[q].x; c += 1.f; }
            if (r[q].y > tau) { s += r[q].y; c += 1.f; }
            if (r[q].z > tau) { s += r[q].z; c += 1.f; }
            if (r[q].w > tau) { s += r[q].w; c += 1.f; }
        }
        float2 sc = block_sum2(s, c, buf2);
        float tn = (sc.x - 1.0f) / sc.y;
        if (!(tn > tau)) break;
        tau = tn;
    }

    if (tid == 0) sh_pos = 0;
    __syncthreads();
#pragma unroll
    for (int q = 0; q < 8; q++) {
        int base = (q * 256 + tid) * 4;
        float vv[4] = {r[q].x, r[q].y, r[q].z, r[q].w};
#pragma unroll
        for (int cmp = 0; cmp < 4; cmp++) {
            float v = vv[cmp] - tau;
            if (v > 0.f) {
                int p = atomicAdd(&sh_pos, 1);
                if (p < CAP) { lidx[p] = base + cmp; lw[p] = v; }
            }
        }
    }
    __syncthreads();
    int total = sh_pos;

    const uint2* M2 = reinterpret_cast<const uint2*>(g_Mh);
    float4 acc = make_float4(0.f, 0.f, 0.f, 0.f);

    if (total <= CAP) {
        int t = 0;
        for (; t + 4 <= total; t += 4) {
#pragma unroll
            for (int u = 0; u < 4; u++) {
                int j = lidx[t + u];
                float w = lw[t + u];
                uint2 m = M2[(size_t)j * 256 + tid];
                float2 f0 = __half22float2(*reinterpret_cast<__half2*>(&m.x));
                float2 f1 = __half22float2(*reinterpret_cast<__half2*>(&m.y));
                acc.x = fmaf(w, f0.x, acc.x);
                acc.y = fmaf(w, f0.y, acc.y);
                acc.z = fmaf(w, f1.x, acc.z);
                acc.w = fmaf(w, f1.y, acc.w);
            }
        }
        for (; t < total; t++) {
            int j = lidx[t];
            float w = lw[t];
            uint2 m = M2[(size_t)j * 256 + tid];
            float2 f0 = __half22float2(*reinterpret_cast<__half2*>(&m.x));
            float2 f1 = __half22float2(*reinterpret_cast<__half2*>(&m.y));
            acc.x = fmaf(w, f0.x, acc.x);
            acc.y = fmaf(w, f0.y, acc.y);
            acc.z = fmaf(w, f1.x, acc.z);
            acc.w = fmaf(w, f1.y, acc.w);
        }
    } else {
        __syncthreads();
#pragma unroll
        for (int q = 0; q < 8; q++) {
            int base = (q * 256 + tid) * 4;
            zbuf[base + 0] = fmaxf(r[q].x - tau, 0.f);
            zbuf[base + 1] = fmaxf(r[q].y - tau, 0.f);
            zbuf[base + 2] = fmaxf(r[q].z - tau, 0.f);
            zbuf[base + 3] = fmaxf(r[q].w - tau, 0.f);
        }
        __syncthreads();
        for (int j = 0; j < MSET; j++) {
            float w = zbuf[j];
            if (w > 0.f) {
                uint2 m = M2[(size_t)j * 256 + tid];
                float2 f0 = __half22float2(*reinterpret_cast<__half2*>(&m.x));
                float2 f1 = __half22float2(*reinterpret_cast<__half2*>(&m.y));
                acc.x = fmaf(w, f0.x, acc.x);
                acc.y = fmaf(w, f0.y, acc.y);
                acc.z = fmaf(w, f1.x, acc.z);
                acc.w = fmaf(w, f1.y, acc.w);
            }
        }
    }

    __half2 h0 = __floats2half2_rn(acc.x, acc.y);
    __half2 h1 = __floats2half2_rn(acc.z, acc.w);
    uint2 u = make_uint2(*reinterpret_cast<unsigned*>(&h0), *reinterpret_cast<unsigned*>(&h1));
    reinterpret_cast<uint2*>(g_FIh)[row * 512 + 256 + tid] = u;
}

// ---------------- launch ----------------
extern "C" void kernel_launch(void* const* d_in, const int* in_sizes, int n_in,
                              void* d_out, int out_size) {
    const float* enc = (const float*)d_in[0];
    const float* mem = (const float*)d_in[1];
    const float* W1 = (const float*)d_in[3];
    const float* b1 = (const float*)d_in[4];
    const float* W2 = (const float*)d_in[5];
    const float* b2 = (const float*)d_in[6];
    float* out = (float*)d_out;

    cudaFuncSetAttribute(gemm_fp16<0, false, false, false>,
                         cudaFuncAttributeMaxDynamicSharedMemorySize, GEMM_SMEM_BYTES);
    cudaFuncSetAttribute(gemm_fp16<3, false, false, false>,
                         cudaFuncAttributeMaxDynamicSharedMemorySize, GEMM_SMEM_BYTES);
    cudaFuncSetAttribute(gemm_fp16<4, true, true, false>,
                         cudaFuncAttributeMaxDynamicSharedMemorySize, GEMM_SMEM_BYTES);
    cudaFuncSetAttribute(gemm_fp16<2, true, false, true>,
                         cudaFuncAttributeMaxDynamicSharedMemorySize, GEMM_SMEM_BYTES);

    // side stream + events (created per call; handles only, no device memory)
    cudaStream_t s2;
    cudaStreamCreateWithFlags(&s2, cudaStreamNonBlocking);
    cudaEvent_t eFork, eJoin;
    cudaEventCreateWithFlags(&eFork, cudaEventDisableTiming);
    cudaEventCreateWithFlags(&eJoin, cudaEventDisableTiming);

    prep_kernel<<<PREP_BLOCKS, 256>>>(enc, mem, W1, W2);

    {   // S = XN @ YN^T   [4096 x 8192], K=1024
        dim3 grid(MSET / 128, BATCH / 128);
        gemm_fp16<0, false, false, false><<<grid, 256, GEMM_SMEM_BYTES>>>(
            nullptr, nullptr, MSET, DIM, DIM, 0);
    }

    // fork: spmv (memory-bound) on side stream, gemm1a (tensor-bound) on main
    cudaEventRecord(eFork, 0);
    cudaStreamWaitEvent(s2, eFork, 0);

    sparsemax_mv_kernel<<<BATCH, 256, 0, s2>>>();

    {   // Hp = FI[:, :1024] @ W1[:, :1024]^T   (enc half; independent of spmv)
        dim3 grid(HID / 128, BATCH / 128);
        gemm_fp16<3, false, false, false><<<grid, 256, GEMM_SMEM_BYTES>>>(
            nullptr, nullptr, HID, DIM, 2 * DIM, 0);
    }

    // join
    cudaEventRecord(eJoin, s2);
    cudaStreamWaitEvent(0, eJoin, 0);

    {   // H = relu(Hp + FI[:, 1024:] @ W1[:, 1024:]^T + b1)
        dim3 grid(HID / 128, BATCH / 128);
        gemm_fp16<4, true, true, false><<<grid, 256, GEMM_SMEM_BYTES>>>(
            b1, nullptr, HID, DIM, 2 * DIM, DIM);
    }
    {   // out = H @ W2^T + b2  [4096 x 1000], K=4096 (N padded to 1024)
        dim3 grid(OUTP / 128, BATCH / 128);
        gemm_fp16<2, true, false, true><<<grid, 256, GEMM_SMEM_BYTES>>>(
            b2, out, OUTD, HID, HID, 0);
    }
    // handles intentionally not destroyed during capture (leak is host-side only,
    // kernel_launch is invoked a bounded number of times by the harness)
}

// round 13
// speedup vs baseline: 1.0421x; 1.0421x over previous
#include <cuda_runtime.h>
#include <cuda_fp16.h>
#include <math.h>
#include <stdint.h>

#define BATCH 4096
#define MSET  8192
#define DIM   1024
#define HID   4096
#define OUTD  1000
#define OUTP  1024
#define CAP   2048

// ---------------- scratch (static device globals: no allocation) ----------------
__device__ __half g_XNh[(size_t)BATCH * DIM];
__device__ __half g_YNh[(size_t)MSET  * DIM];
__device__ __half g_Mh [(size_t)MSET  * DIM];     // raw memory_set in half
__device__ float  g_S  [(size_t)BATCH * MSET];
__device__ __half g_FIh[(size_t)BATCH * 2 * DIM];
__device__ __half g_Hh [(size_t)BATCH * HID];
__device__ __half g_W1h[(size_t)HID * 2 * DIM];
__device__ __half g_W2h[(size_t)OUTP * HID];     // rows 1000..1023 zero-padded

// ---------------- helpers ----------------
__device__ __forceinline__ void cpa16(void* sdst, const void* gsrc) {
    unsigned s = (unsigned)__cvta_generic_to_shared(sdst);
    asm volatile("cp.async.cg.shared.global [%0], [%1], 16;\n" :: "r"(s), "l"(gsrc) : "memory");
}
#define CPA_COMMIT() asm volatile("cp.async.commit_group;\n" ::: "memory")
#define CPA_WAIT1()  asm volatile("cp.async.wait_group 1;\n" ::: "memory")

__device__ __forceinline__ void ldsm_x4(unsigned& r0, unsigned& r1, unsigned& r2, unsigned& r3,
                                        const __half* p) {
    unsigned a = (unsigned)__cvta_generic_to_shared(p);
    asm volatile("ldmatrix.sync.aligned.m8n8.x4.shared.b16 {%0,%1,%2,%3}, [%4];"
                 : "=r"(r0), "=r"(r1), "=r"(r2), "=r"(r3) : "r"(a));
}

__device__ __forceinline__ void mma_fp16(float c[4], const unsigned a[4], const unsigned b[2]) {
    asm volatile(
        "mma.sync.aligned.m16n8k16.row.col.f32.f16.f16.f32 "
        "{%0,%1,%2,%3}, {%4,%5,%6,%7}, {%8,%9}, {%0,%1,%2,%3};\n"
        : "+f"(c[0]), "+f"(c[1]), "+f"(c[2]), "+f"(c[3])
        : "r"(a[0]), "r"(a[1]), "r"(a[2]), "r"(a[3]), "r"(b[0]), "r"(b[1]));
}

__device__ __forceinline__ float warp_sum(float v) {
#pragma unroll
    for (int o = 16; o > 0; o >>= 1) v += __shfl_down_sync(0xffffffffu, v, o);
    return v;
}
__device__ __forceinline__ float warp_max(float v) {
#pragma unroll
    for (int o = 16; o > 0; o >>= 1) v = fmaxf(v, __shfl_down_sync(0xffffffffu, v, o));
    return v;
}
__device__ __forceinline__ float block_sum(float v, float* buf) {
    int tid = threadIdx.x, w = tid >> 5, l = tid & 31;
    v = warp_sum(v);
    __syncthreads();
    if (l == 0) buf[w] = v;
    __syncthreads();
    if (tid == 0) {
        float s = 0.f;
#pragma unroll
        for (int i = 0; i < 8; i++) s += buf[i];
        buf[0] = s;
    }
    __syncthreads();
    return buf[0];
}
__device__ __forceinline__ float2 block_sum2(float a, float b, float2* buf) {
    int tid = threadIdx.x, w = tid >> 5, l = tid & 31;
#pragma unroll
    for (int o = 16; o > 0; o >>= 1) {
        a += __shfl_down_sync(0xffffffffu, a, o);
        b += __shfl_down_sync(0xffffffffu, b, o);
    }
    __syncthreads();
    if (l == 0) buf[w] = make_float2(a, b);
    __syncthreads();
    if (tid == 0) {
        float2 s = make_float2(0.f, 0.f);
#pragma unroll
        for (int i = 0; i < 8; i++) { s.x += buf[i].x; s.y += buf[i].y; }
        buf[0] = s;
    }
    __syncthreads();
    return buf[0];
}
__device__ __forceinline__ float block_max(float v, float* buf) {
    int tid = threadIdx.x, w = tid >> 5, l = tid & 31;
    v = warp_max(v);
    __syncthreads();
    if (l == 0) buf[w] = v;
    __syncthreads();
    if (tid == 0) {
        float s = buf[0];
#pragma unroll
        for (int i = 1; i < 8; i++) s = fmaxf(s, buf[i]);
        buf[0] = s;
    }
    __syncthreads();
    return buf[0];
}

// ---------------- 1a) normalize prep (critical path for gemm0) ----------------
__global__ __launch_bounds__(256) void prep_norm(const float* __restrict__ enc,
                                                 const float* __restrict__ mem) {
    __shared__ float buf[8];
    int b = blockIdx.x;
    int tid = threadIdx.x;

    bool is_enc = (b < BATCH);
    const float* src = is_enc ? enc : mem;
    __half* dst = is_enc ? g_XNh : g_YNh;
    size_t row = is_enc ? b : (b - BATCH);
    const float4* s4 = reinterpret_cast<const float4*>(src) + row * (DIM / 4);
    float4 v = s4[tid];

    {
        __half2 h0 = __floats2half2_rn(v.x, v.y);
        __half2 h1 = __floats2half2_rn(v.z, v.w);
        uint2 u = make_uint2(*reinterpret_cast<unsigned*>(&h0), *reinterpret_cast<unsigned*>(&h1));
        if (is_enc)
            reinterpret_cast<uint2*>(g_FIh)[row * 512 + tid] = u;
        else
            reinterpret_cast<uint2*>(g_Mh)[row * 256 + tid] = u;
    }

    float ss = v.x * v.x + v.y * v.y + v.z * v.z + v.w * v.w;
    ss = block_sum(ss, buf);
    float inv = rsqrtf(ss + 1e-6f);
    __half2 h0 = __floats2half2_rn(v.x * inv, v.y * inv);
    __half2 h1 = __floats2half2_rn(v.z * inv, v.w * inv);
    uint2 u = make_uint2(*reinterpret_cast<unsigned*>(&h0), *reinterpret_cast<unsigned*>(&h1));
    reinterpret_cast<uint2*>(dst)[row * (DIM / 4) + tid] = u;
}

// ---------------- 1b) weight conversion (off critical path; side stream) ----------
// blocks [0, 8192): W1 chunk -> g_W1h ; [8192, 12288): W2 chunk -> g_W2h (padded)
__global__ __launch_bounds__(256) void prep_weights(const float* __restrict__ W1,
                                                    const float* __restrict__ W2) {
    int b = blockIdx.x;
    int tid = threadIdx.x;
    if (b < 8192) {
        int i = b * 256 + tid;
        float4 v = reinterpret_cast<const float4*>(W1)[i];
        __half2 h0 = __floats2half2_rn(v.x, v.y);
        __half2 h1 = __floats2half2_rn(v.z, v.w);
        uint2 u = make_uint2(*reinterpret_cast<unsigned*>(&h0), *reinterpret_cast<unsigned*>(&h1));
        reinterpret_cast<uint2*>(g_W1h)[i] = u;
    } else {
        int i = (b - 8192) * 256 + tid;
        uint2 u = make_uint2(0u, 0u);
        if (i < OUTD * HID / 4) {
            float4 v = reinterpret_cast<const float4*>(W2)[i];
            __half2 h0 = __floats2half2_rn(v.x, v.y);
            __half2 h1 = __floats2half2_rn(v.z, v.w);
            u = make_uint2(*reinterpret_cast<unsigned*>(&h0), *reinterpret_cast<unsigned*>(&h1));
        }
        reinterpret_cast<uint2*>(g_W2h)[i] = u;
    }
}

// ---------------- 2) fp16 tensor-core NT GEMM (R11 config — frozen) ----------------
// 128x128 CTA tile, BK=64, 8 warps (4M x 2N, 32x64 warp tile), ldmatrix.x4,
// mma m16n8k16, 3-stage cp.async, 256 threads, 2 CTAs/SM.
#define HSTRIDE 72
#define MAT_H (128 * HSTRIDE)
#define STAGE_H (2 * MAT_H)
#define NST 3
#define GEMM_SMEM_BYTES (NST * STAGE_H * 2)   // 110592

template <int MODE, bool BIAS, bool RELU, bool NGUARD>
__global__ __launch_bounds__(256, 2) void gemm_fp16(const float* __restrict__ bias,
                                                    float* __restrict__ Cext,
                                                    int N, int K) {
    extern __shared__ __half sh[];

    const __half* A;
    const __half* B;
    if (MODE == 0)      { A = g_XNh; B = g_YNh; }
    else if (MODE == 1) { A = g_FIh; B = g_W1h; }
    else                { A = g_Hh;  B = g_W2h; }

    int tid = threadIdx.x;
    int lane = tid & 31;
    int warp = tid >> 5;
    int wm = warp & 3, wn = warp >> 2;
    int g = lane >> 2, tig = lane & 3;

    int bm = blockIdx.y * 128;
    int bn = blockIdx.x * 128;

    float acc[2][8][4];
#pragma unroll
    for (int i = 0; i < 2; i++)
#pragma unroll
        for (int j = 0; j < 8; j++)
#pragma unroll
            for (int q = 0; q < 4; q++) acc[i][j][q] = 0.f;

    int kT = K >> 6;
    const __half* Abase = A + (size_t)bm * K;
    const __half* Bbase = B + (size_t)bn * K;

    auto load_stage = [&](int t) {
        int st = t % NST;
        __half* sA = sh + st * STAGE_H;
        __half* sB = sA + MAT_H;
        const __half* Ag = Abase + t * 64;
        const __half* Bg = Bbase + t * 64;
#pragma unroll
        for (int it = 0; it < 4; it++) {
            int idx = it * 256 + tid;
            int row = idx >> 3, ch = idx & 7;
            cpa16(sA + row * HSTRIDE + ch * 8, Ag + (size_t)row * K + ch * 8);
            cpa16(sB + row * HSTRIDE + ch * 8, Bg + (size_t)row * K + ch * 8);
        }
    };

    load_stage(0); CPA_COMMIT();
    load_stage(1); CPA_COMMIT();

    int a_row = lane & 15;
    int a_kh  = (lane >> 4) << 3;
    int b_q   = lane >> 3;
    int b_row = (b_q >> 1) * 8 + (lane & 7);
    int b_kh  = (b_q & 1) << 3;

    for (int t = 0; t < kT; t++) {
        CPA_WAIT1();
        __syncthreads();

        if (t + 2 < kT) { load_stage(t + 2); CPA_COMMIT(); }

        const __half* as = sh + (t % NST) * STAGE_H + (wm * 32) * HSTRIDE;
        const __half* bs = sh + (t % NST) * STAGE_H + MAT_H + (wn * 64) * HSTRIDE;

#pragma unroll
        for (int kk = 0; kk < 4; kk++) {
            int kb = kk * 16;
            unsigned a[2][4], b[8][2];
#pragma unroll
            for (int i = 0; i < 2; i++)
                ldsm_x4(a[i][0], a[i][1], a[i][2], a[i][3],
                        as + (i * 16 + a_row) * HSTRIDE + kb + a_kh);
#pragma unroll
            for (int jj = 0; jj < 4; jj++)
                ldsm_x4(b[2 * jj][0], b[2 * jj][1], b[2 * jj + 1][0], b[2 * jj + 1][1],
                        bs + (jj * 16 + b_row) * HSTRIDE + kb + b_kh);
#pragma unroll
            for (int i = 0; i < 2; i++)
#pragma unroll
                for (int j = 0; j < 8; j++)
                    mma_fp16(acc[i][j], a[i], b[j]);
        }
    }

    // epilogue
#pragma unroll
    for (int i = 0; i < 2; i++) {
        int r0 = bm + wm * 32 + i * 16 + g;
#pragma unroll
        for (int j = 0; j < 8; j++) {
            int col = bn + wn * 64 + j * 8 + tig * 2;
            if (NGUARD && col >= N) continue;
            float bv0 = 0.f, bv1 = 0.f;
            if (BIAS) { bv0 = __ldg(bias + col); bv1 = __ldg(bias + col + 1); }
            float v0 = acc[i][j][0] + bv0;
            float v1 = acc[i][j][1] + bv1;
            float v2 = acc[i][j][2] + bv0;
            float v3 = acc[i][j][3] + bv1;
            if (RELU) {
                v0 = fmaxf(v0, 0.f); v1 = fmaxf(v1, 0.f);
                v2 = fmaxf(v2, 0.f); v3 = fmaxf(v3, 0.f);
            }
            if (MODE == 1) {
                __half2 h0 = __floats2half2_rn(v0, v1);
                __half2 h1 = __floats2half2_rn(v2, v3);
                *reinterpret_cast<unsigned*>(g_Hh + (size_t)r0 * N + col) =
                    *reinterpret_cast<unsigned*>(&h0);
                *reinterpret_cast<unsigned*>(g_Hh + (size_t)(r0 + 8) * N + col) =
                    *reinterpret_cast<unsigned*>(&h1);
            } else {
                float* C = (MODE == 0) ? g_S : Cext;
                *reinterpret_cast<float2*>(C + (size_t)r0 * N + col)       = make_float2(v0, v1);
                *reinterpret_cast<float2*>(C + (size_t)(r0 + 8) * N + col) = make_float2(v2, v3);
            }
        }
    }
}

// ---------------- 3) fused sparsemax + memory_vector -> FIh right half ----------------
__global__ __launch_bounds__(256) void sparsemax_mv_kernel() {
    __shared__ float zbuf[MSET];
    __shared__ float bufA[8];
    __shared__ float2 buf2[8];
    __shared__ int sh_pos;
    int* lidx = reinterpret_cast<int*>(zbuf);
    float* lw  = zbuf + CAP;

    size_t row = blockIdx.x;
    int tid = threadIdx.x;
    const float4* s4 = reinterpret_cast<const float4*>(g_S + row * (size_t)MSET);

    float4 r[8];
    float mx = -1e30f;
#pragma unroll
    for (int q = 0; q < 8; q++) {
        r[q] = s4[q * 256 + tid];
        mx = fmaxf(mx, fmaxf(fmaxf(r[q].x, r[q].y), fmaxf(r[q].z, r[q].w)));
    }
    mx = block_max(mx, bufA);

    float tau = mx - 1.0f;
    for (int it = 0; it < 64; ++it) {
        float s = 0.f, c = 0.f;
#pragma unroll
        for (int q = 0; q < 8; q++) {
            if (r[q].x > tau) { s += r[q].x; c += 1.f; }
            if (r[q].y > tau) { s += r[q].y; c += 1.f; }
            if (r[q].z > tau) { s += r[q].z; c += 1.f; }
            if (r[q].w > tau) { s += r[q].w; c += 1.f; }
        }
        float2 sc = block_sum2(s, c, buf2);
        float tn = (sc.x - 1.0f) / sc.y;
        if (!(tn > tau)) break;
        tau = tn;
    }

    if (tid == 0) sh_pos = 0;
    __syncthreads();
#pragma unroll
    for (int q = 0; q < 8; q++) {
        int base = (q * 256 + tid) * 4;
        float vv[4] = {r[q].x, r[q].y, r[q].z, r[q].w};
#pragma unroll
        for (int cmp = 0; cmp < 4; cmp++) {
            float v = vv[cmp] - tau;
            if (v > 0.f) {
                int p = atomicAdd(&sh_pos, 1);
                if (p < CAP) { lidx[p] = base + cmp; lw[p] = v; }
            }
        }
    }
    __syncthreads();
    int total = sh_pos;

    const uint2* M2 = reinterpret_cast<const uint2*>(g_Mh);
    float4 acc = make_float4(0.f, 0.f, 0.f, 0.f);

    if (total <= CAP) {
        int t = 0;
        for (; t + 4 <= total; t += 4) {
#pragma unroll
            for (int u = 0; u < 4; u++) {
                int j = lidx[t + u];
                float w = lw[t + u];
                uint2 m = M2[(size_t)j * 256 + tid];
                float2 f0 = __half22float2(*reinterpret_cast<__half2*>(&m.x));
                float2 f1 = __half22float2(*reinterpret_cast<__half2*>(&m.y));
                acc.x = fmaf(w, f0.x, acc.x);
                acc.y = fmaf(w, f0.y, acc.y);
                acc.z = fmaf(w, f1.x, acc.z);
                acc.w = fmaf(w, f1.y, acc.w);
            }
        }
        for (; t < total; t++) {
            int j = lidx[t];
            float w = lw[t];
            uint2 m = M2[(size_t)j * 256 + tid];
            float2 f0 = __half22float2(*reinterpret_cast<__half2*>(&m.x));
            float2 f1 = __half22float2(*reinterpret_cast<__half2*>(&m.y));
            acc.x = fmaf(w, f0.x, acc.x);
            acc.y = fmaf(w, f0.y, acc.y);
            acc.z = fmaf(w, f1.x, acc.z);
            acc.w = fmaf(w, f1.y, acc.w);
        }
    } else {
        __syncthreads();
#pragma unroll
        for (int q = 0; q < 8; q++) {
            int base = (q * 256 + tid) * 4;
            zbuf[base + 0] = fmaxf(r[q].x - tau, 0.f);
            zbuf[base + 1] = fmaxf(r[q].y - tau, 0.f);
            zbuf[base + 2] = fmaxf(r[q].z - tau, 0.f);
            zbuf[base + 3] = fmaxf(r[q].w - tau, 0.f);
        }
        __syncthreads();
        for (int j = 0; j < MSET; j++) {
            float w = zbuf[j];
            if (w > 0.f) {
                uint2 m = M2[(size_t)j * 256 + tid];
                float2 f0 = __half22float2(*reinterpret_cast<__half2*>(&m.x));
                float2 f1 = __half22float2(*reinterpret_cast<__half2*>(&m.y));
                acc.x = fmaf(w, f0.x, acc.x);
                acc.y = fmaf(w, f0.y, acc.y);
                acc.z = fmaf(w, f1.x, acc.z);
                acc.w = fmaf(w, f1.y, acc.w);
            }
        }
    }

    __half2 h0 = __floats2half2_rn(acc.x, acc.y);
    __half2 h1 = __floats2half2_rn(acc.z, acc.w);
    uint2 u = make_uint2(*reinterpret_cast<unsigned*>(&h0), *reinterpret_cast<unsigned*>(&h1));
    reinterpret_cast<uint2*>(g_FIh)[row * 512 + 256 + tid] = u;
}

// ---------------- launch ----------------
extern "C" void kernel_launch(void* const* d_in, const int* in_sizes, int n_in,
                              void* d_out, int out_size) {
    const float* enc = (const float*)d_in[0];
    const float* mem = (const float*)d_in[1];
    const float* W1 = (const float*)d_in[3];
    const float* b1 = (const float*)d_in[4];
    const float* W2 = (const float*)d_in[5];
    const float* b2 = (const float*)d_in[6];
    float* out = (float*)d_out;

    cudaFuncSetAttribute(gemm_fp16<0, false, false, false>,
                         cudaFuncAttributeMaxDynamicSharedMemorySize, GEMM_SMEM_BYTES);
    cudaFuncSetAttribute(gemm_fp16<1, true, true, false>,
                         cudaFuncAttributeMaxDynamicSharedMemorySize, GEMM_SMEM_BYTES);
    cudaFuncSetAttribute(gemm_fp16<2, true, false, true>,
                         cudaFuncAttributeMaxDynamicSharedMemorySize, GEMM_SMEM_BYTES);

    // side stream for the weight conversion (no data deps with the main chain
    // until gemm1); handles only — no device memory
    cudaStream_t s2;
    cudaStreamCreateWithFlags(&s2, cudaStreamNonBlocking);
    cudaEvent_t eFork, eW;
    cudaEventCreateWithFlags(&eFork, cudaEventDisableTiming);
    cudaEventCreateWithFlags(&eW, cudaEventDisableTiming);

    // graph capture requires the side stream to be forked from the origin stream
    cudaEventRecord(eFork, 0);
    cudaStreamWaitEvent(s2, eFork, 0);
    prep_weights<<<12288, 256, 0, s2>>>(W1, W2);
    cudaEventRecord(eW, s2);

    prep_norm<<<BATCH + MSET, 256>>>(enc, mem);

    {   // S = XN @ YN^T   [4096 x 8192], K=1024
        dim3 grid(MSET / 128, BATCH / 128);
        gemm_fp16<0, false, false, false><<<grid, 256, GEMM_SMEM_BYTES>>>(nullptr, nullptr, MSET, DIM);
    }

    sparsemax_mv_kernel<<<BATCH, 256>>>();

    // join: gemm1 needs g_W1h
    cudaStreamWaitEvent(0, eW, 0);

    {   // H = relu(FI @ W1^T + b1)  [4096 x 4096], K=2048
        dim3 grid(HID / 128, BATCH / 128);
        gemm_fp16<1, true, true, false><<<grid, 256, GEMM_SMEM_BYTES>>>(b1, nullptr, HID, 2 * DIM);
    }
    {   // out = H @ W2^T + b2  [4096 x 1000], K=4096 (N padded to 1024)
        dim3 grid(OUTP / 128, BATCH / 128);
        gemm_fp16<2, true, false, true><<<grid, 256, GEMM_SMEM_BYTES>>>(b2, out, OUTD, HID);
    }
}